// round 7
// baseline (speedup 1.0000x reference)
#include <cuda_runtime.h>
#include <math.h>

#define MM 256
#define DD 768
#define THRESH 0.3f
#define EPSF 1e-8f

// ---------------- device scratch (no allocations allowed) ----------------
__device__ float g_nm2[MM];          // ||m_i||^2 (raw)
__device__ float g_rnm[MM];          // 1/max(||m_i||, EPS)
__device__ float g_Sm[MM];           // sum(m_i)
__device__ float g_kx[MM];           // dot(m_i, x)
__device__ float g_mask[MM];
__device__ float g_nx, g_Sx;
__device__ float g_km[MM * MM];      // mem @ mem^T
__device__ float g_sT[MM * MM];      // s transposed: g_sT[i*MM + a]

// ---------------- K1: gram tiles + row/x stats in one grid ----------------
// 513 blocks x 256 threads. blocks [0,256): 16x16 gram tiles.
// blocks [256,512): per-row stats. block 512: x stats. No cross-block deps.
__global__ void k_prep(const float* __restrict__ x, const float* __restrict__ mem) {
    int b = blockIdx.x, t = threadIdx.x;

    if (b < 256) {
        __shared__ float sA[16][65];
        __shared__ float sB[16][65];
        int ty = t >> 4, tx = t & 15;
        int r0 = (b >> 4) * 16, c0 = (b & 15) * 16;
        float acc = 0.f;
        for (int k0 = 0; k0 < DD; k0 += 64) {
#pragma unroll
            for (int q = 0; q < 4; q++) {
                int idx = t + q * 256;
                int rr = idx >> 6, cc = idx & 63;
                sA[rr][cc] = mem[(r0 + rr) * DD + k0 + cc];
                sB[rr][cc] = mem[(c0 + rr) * DD + k0 + cc];
            }
            __syncthreads();
#pragma unroll
            for (int k = 0; k < 64; k++)
                acc = fmaf(sA[ty][k], sB[tx][k], acc);
            __syncthreads();
        }
        g_km[(r0 + ty) * MM + (c0 + tx)] = acc;
    } else {
        int r = b - 256;
        float s0 = 0.f, s1 = 0.f, s2 = 0.f;
        if (r < MM) {
            const float* row = mem + r * DD;
            for (int d = t; d < DD; d += 256) {
                float v = row[d], xv = x[d];
                s0 = fmaf(v, v, s0);
                s1 += v;
                s2 = fmaf(v, xv, s2);
            }
        } else {
            for (int d = t; d < DD; d += 256) {
                float xv = x[d];
                s0 = fmaf(xv, xv, s0);
                s1 += xv;
            }
        }
        __shared__ float sh[3][8];
#pragma unroll
        for (int o = 16; o; o >>= 1) {
            s0 += __shfl_down_sync(0xffffffffu, s0, o);
            s1 += __shfl_down_sync(0xffffffffu, s1, o);
            s2 += __shfl_down_sync(0xffffffffu, s2, o);
        }
        if ((t & 31) == 0) { int w = t >> 5; sh[0][w] = s0; sh[1][w] = s1; sh[2][w] = s2; }
        __syncthreads();
        if (t == 0) {
            float a = 0.f, c = 0.f, e = 0.f;
            for (int w = 0; w < 8; w++) { a += sh[0][w]; c += sh[1][w]; e += sh[2][w]; }
            if (r < MM) {
                g_nm2[r] = a;
                g_rnm[r] = 1.f / fmaxf(sqrtf(a), EPSF);
                g_Sm[r] = c;
                g_kx[r] = e;
            } else {
                g_nx = fmaxf(sqrtf(a), EPSF);
                g_Sx = c;
            }
        }
    }
}

// ---------------- K2: block i -> mask/cnt/A2 (local) + A1[i] + s[:, i] -----
// Every block recomputes mask/cnt/A2 from K1 outputs (O(M) cheap; avoids an
// extra kernel launch, which costs ~5-6us on this chip).
__global__ void k_s(void) {
    __shared__ float red[3][8];
    __shared__ float sh_A1, sh_cnt, sh_A2;
    int i = blockIdx.x, t = threadIdx.x;

    float nx = g_nx;
    float rnmt = g_rnm[t];
    float mx_t = g_kx[t] * rnmt / nx;          // cos(m_t, x)
    float mk = (mx_t > THRESH) ? 1.f : 0.f;
    float w = mk * rnmt;
    if (i == 0) g_mask[t] = mk;

    float kmv = g_km[i * MM + t];              // km[i, t], coalesced; symmetric

    // parallel reductions: cnt, A2, A1[i]
    float r0 = mk;
    float r1 = mk * g_Sm[t] * rnmt;
    float r2 = kmv * w;
#pragma unroll
    for (int o = 16; o; o >>= 1) {
        r0 += __shfl_down_sync(0xffffffffu, r0, o);
        r1 += __shfl_down_sync(0xffffffffu, r1, o);
        r2 += __shfl_down_sync(0xffffffffu, r2, o);
    }
    if ((t & 31) == 0) { int wi = t >> 5; red[0][wi] = r0; red[1][wi] = r1; red[2][wi] = r2; }
    __syncthreads();
    if (t == 0) {
        float a = 0.f, b = 0.f, c = 0.f;
        for (int wi = 0; wi < 8; wi++) { a += red[0][wi]; b += red[1][wi]; c += red[2][wi]; }
        sh_cnt = a; sh_A2 = b; sh_A1 = c;
    }
    __syncthreads();

    // per-a scalar for a = t (note mx[i] term, i fixed per block)
    float rnmi = g_rnm[i];
    float kxi = g_kx[i];
    float c = kmv * rnmi * rnmt + kxi * rnmi / nx;
    float nkp = sqrtf(fmaxf(g_nm2[i] + 2.f * c * g_Sm[i] + (float)DD * c * c,
                            EPSF * EPSF));
    float ckx = (kxi + c * g_Sx) / (nkp * nx);
    float cnt = sh_cnt;
    float mean = (cnt > 0.f) ? (sh_A1 + c * sh_A2) / (nkp * fmaxf(cnt, 1.f)) : 0.f;
    g_sT[i * MM + t] = c + ckx + mean;         // coalesced
}

// ---------------- K3: streaming broadcast-add (HBM-bound) ------------------
// grid (i=256, a-chunk=8), 192 threads; thread owns one float4 of the D row.
__global__ void k_out(const float4* __restrict__ memv,
                      const float4* __restrict__ noise,
                      float4* __restrict__ out) {
    __shared__ float s_sh[32];
    __shared__ float m_sh[32];
    int i = blockIdx.x;
    int a0 = blockIdx.y << 5;
    int t = threadIdx.x;

    float4 mv = memv[i * 192 + t];

    if (t < 32) {
        m_sh[t] = g_mask[a0 + t];
        s_sh[t] = g_sT[i * MM + a0 + t];   // one 128B line
    }
    __syncthreads();

#pragma unroll 4
    for (int q = 0; q < 32; q++) {
        int a = a0 + q;
        int base = (a * MM + i) * 192 + t;   // < 2^31
        if (m_sh[q] != 0.f) {
            float s = s_sh[q];
            float4 nz = __ldcs(&noise[base]);    // evict-first: read-once
            float4 r;
            r.x = mv.x + s + nz.x;
            r.y = mv.y + s + nz.y;
            r.z = mv.z + s + nz.z;
            r.w = mv.w + s + nz.w;
            __stcs(&out[base], r);               // streaming store
        } else {
            __stcs(&out[base], make_float4(0.f, 0.f, 0.f, 0.f));
        }
    }
}

// ---------------- launch ----------------
extern "C" void kernel_launch(void* const* d_in, const int* in_sizes, int n_in,
                              void* d_out, int out_size) {
    const float* x     = (const float*)d_in[0];
    const float* mem   = (const float*)d_in[1];
    const float* noise = (const float*)d_in[2];
    float* out = (float*)d_out;

    k_prep<<<513, 256>>>(x, mem);
    k_s<<<MM, 256>>>();
    k_out<<<dim3(MM, 8), 192>>>((const float4*)mem, (const float4*)noise,
                                (float4*)out);
}

// round 8
// speedup vs baseline: 1.0227x; 1.0227x over previous
#include <cuda_runtime.h>
#include <math.h>

#define MM 256
#define DD 768
#define THRESH 0.3f
#define EPSF 1e-8f
#define KSPLIT 4
#define KPER (DD / KSPLIT)      // 192 k per gram block

// ---------------- device scratch (no allocations allowed) ----------------
__device__ float g_nm2[MM];            // ||m_i||^2
__device__ float g_rnm[MM];            // 1/max(||m_i||, EPS)
__device__ float g_Sm[MM];             // sum(m_i)
__device__ float g_kx[MM];             // dot(m_i, x)
__device__ float g_mask[MM];
__device__ float g_nx, g_Sx;
__device__ float g_kmp[KSPLIT][MM * MM];  // gram partials over K-splits
__device__ float g_sT[MM * MM];        // s transposed: g_sT[i*MM + a]

// ---------------- K1: gram (reg-tiled, K-split) + row/x stats -------------
// 513 blocks x 256 threads.
//   blocks [0,256):   gram partials. b = split*64 + tile; tile -> 32x32 output
//                     tile, split -> K-range [split*192, split*192+192).
//                     Each thread: 2x2 outputs, float4 shared reads.
//   blocks [256,512): per-row stats.  block 512: x stats.
__global__ void k_prep(const float* __restrict__ x, const float* __restrict__ mem) {
    int b = blockIdx.x, t = threadIdx.x;

    if (b < 256) {
        __shared__ float4 sA4[32][9];   // 32 rows x 8 float4 (+1 pad)
        __shared__ float4 sB4[32][9];
        int split = b >> 6;
        int tile = b & 63;
        int r0 = (tile >> 3) * 32, c0 = (tile & 7) * 32;
        int tx = t & 15, ty = t >> 4;
        int lr = t >> 3, lc = t & 7;    // loader: row, float4-col
        const float4* mem4 = (const float4*)mem;   // row stride 192 float4
        float acc00 = 0.f, acc01 = 0.f, acc10 = 0.f, acc11 = 0.f;

        for (int kc = 0; kc < KPER; kc += 32) {
            int kq0 = (split * KPER + kc) >> 2;    // float4 offset in row
            sA4[lr][lc] = mem4[(r0 + lr) * 192 + kq0 + lc];
            sB4[lr][lc] = mem4[(c0 + lr) * 192 + kq0 + lc];
            __syncthreads();
#pragma unroll
            for (int kq = 0; kq < 8; kq++) {
                float4 a0 = sA4[ty][kq];
                float4 a1 = sA4[ty + 16][kq];
                float4 b0 = sB4[tx][kq];
                float4 b1 = sB4[tx + 16][kq];
                acc00 = fmaf(a0.x, b0.x, acc00); acc00 = fmaf(a0.y, b0.y, acc00);
                acc00 = fmaf(a0.z, b0.z, acc00); acc00 = fmaf(a0.w, b0.w, acc00);
                acc01 = fmaf(a0.x, b1.x, acc01); acc01 = fmaf(a0.y, b1.y, acc01);
                acc01 = fmaf(a0.z, b1.z, acc01); acc01 = fmaf(a0.w, b1.w, acc01);
                acc10 = fmaf(a1.x, b0.x, acc10); acc10 = fmaf(a1.y, b0.y, acc10);
                acc10 = fmaf(a1.z, b0.z, acc10); acc10 = fmaf(a1.w, b0.w, acc10);
                acc11 = fmaf(a1.x, b1.x, acc11); acc11 = fmaf(a1.y, b1.y, acc11);
                acc11 = fmaf(a1.z, b1.z, acc11); acc11 = fmaf(a1.w, b1.w, acc11);
            }
            __syncthreads();
        }
        float* dst = g_kmp[split];
        dst[(r0 + ty) * MM + c0 + tx]           = acc00;
        dst[(r0 + ty) * MM + c0 + tx + 16]      = acc01;
        dst[(r0 + ty + 16) * MM + c0 + tx]      = acc10;
        dst[(r0 + ty + 16) * MM + c0 + tx + 16] = acc11;
    } else {
        int r = b - 256;
        float s0 = 0.f, s1 = 0.f, s2 = 0.f;
        if (r < MM) {
            const float* row = mem + r * DD;
            for (int d = t; d < DD; d += 256) {
                float v = row[d], xv = x[d];
                s0 = fmaf(v, v, s0);
                s1 += v;
                s2 = fmaf(v, xv, s2);
            }
        } else {
            for (int d = t; d < DD; d += 256) {
                float xv = x[d];
                s0 = fmaf(xv, xv, s0);
                s1 += xv;
            }
        }
        __shared__ float sh[3][8];
#pragma unroll
        for (int o = 16; o; o >>= 1) {
            s0 += __shfl_down_sync(0xffffffffu, s0, o);
            s1 += __shfl_down_sync(0xffffffffu, s1, o);
            s2 += __shfl_down_sync(0xffffffffu, s2, o);
        }
        if ((t & 31) == 0) { int w = t >> 5; sh[0][w] = s0; sh[1][w] = s1; sh[2][w] = s2; }
        __syncthreads();
        if (t == 0) {
            float a = 0.f, c = 0.f, e = 0.f;
            for (int w = 0; w < 8; w++) { a += sh[0][w]; c += sh[1][w]; e += sh[2][w]; }
            if (r < MM) {
                g_nm2[r] = a;
                g_rnm[r] = 1.f / fmaxf(sqrtf(a), EPSF);
                g_Sm[r] = c;
                g_kx[r] = e;
            } else {
                g_nx = fmaxf(sqrtf(a), EPSF);
                g_Sx = c;
            }
        }
    }
}

// ---------------- K2: block i -> mask/cnt/A2 (local) + A1[i] + s[:, i] -----
__global__ void k_s(void) {
    __shared__ float red[3][8];
    __shared__ float sh_A1, sh_cnt, sh_A2;
    int i = blockIdx.x, t = threadIdx.x;

    float nx = g_nx;
    float rnmt = g_rnm[t];
    float mx_t = g_kx[t] * rnmt / nx;
    float mk = (mx_t > THRESH) ? 1.f : 0.f;
    float w = mk * rnmt;
    if (i == 0) g_mask[t] = mk;

    int off = i * MM + t;
    float kmv = g_kmp[0][off] + g_kmp[1][off] + g_kmp[2][off] + g_kmp[3][off];

    float r0 = mk;
    float r1 = mk * g_Sm[t] * rnmt;
    float r2 = kmv * w;
#pragma unroll
    for (int o = 16; o; o >>= 1) {
        r0 += __shfl_down_sync(0xffffffffu, r0, o);
        r1 += __shfl_down_sync(0xffffffffu, r1, o);
        r2 += __shfl_down_sync(0xffffffffu, r2, o);
    }
    if ((t & 31) == 0) { int wi = t >> 5; red[0][wi] = r0; red[1][wi] = r1; red[2][wi] = r2; }
    __syncthreads();
    if (t == 0) {
        float a = 0.f, bb = 0.f, c = 0.f;
        for (int wi = 0; wi < 8; wi++) { a += red[0][wi]; bb += red[1][wi]; c += red[2][wi]; }
        sh_cnt = a; sh_A2 = bb; sh_A1 = c;
    }
    __syncthreads();

    float rnmi = g_rnm[i];
    float kxi = g_kx[i];
    float c = kmv * rnmi * rnmt + kxi * rnmi / nx;
    float nkp = sqrtf(fmaxf(g_nm2[i] + 2.f * c * g_Sm[i] + (float)DD * c * c,
                            EPSF * EPSF));
    float ckx = (kxi + c * g_Sx) / (nkp * nx);
    float cnt = sh_cnt;
    float mean = (cnt > 0.f) ? (sh_A1 + c * sh_A2) / (nkp * fmaxf(cnt, 1.f)) : 0.f;
    g_sT[i * MM + t] = c + ckx + mean;
}

// ---------------- K3: streaming broadcast-add (HBM-bound) ------------------
__global__ void k_out(const float4* __restrict__ memv,
                      const float4* __restrict__ noise,
                      float4* __restrict__ out) {
    __shared__ float s_sh[32];
    __shared__ float m_sh[32];
    int i = blockIdx.x;
    int a0 = blockIdx.y << 5;
    int t = threadIdx.x;

    float4 mv = memv[i * 192 + t];

    if (t < 32) {
        m_sh[t] = g_mask[a0 + t];
        s_sh[t] = g_sT[i * MM + a0 + t];
    }
    __syncthreads();

#pragma unroll 4
    for (int q = 0; q < 32; q++) {
        int a = a0 + q;
        int base = (a * MM + i) * 192 + t;
        if (m_sh[q] != 0.f) {
            float s = s_sh[q];
            float4 nz = __ldcs(&noise[base]);
            float4 r;
            r.x = mv.x + s + nz.x;
            r.y = mv.y + s + nz.y;
            r.z = mv.z + s + nz.z;
            r.w = mv.w + s + nz.w;
            __stcs(&out[base], r);
        } else {
            __stcs(&out[base], make_float4(0.f, 0.f, 0.f, 0.f));
        }
    }
}

// ---------------- launch ----------------
extern "C" void kernel_launch(void* const* d_in, const int* in_sizes, int n_in,
                              void* d_out, int out_size) {
    const float* x     = (const float*)d_in[0];
    const float* mem   = (const float*)d_in[1];
    const float* noise = (const float*)d_in[2];
    float* out = (float*)d_out;

    k_prep<<<513, 256>>>(x, mem);
    k_s<<<MM, 256>>>();
    k_out<<<dim3(MM, 8), 192>>>((const float4*)mem, (const float4*)noise,
                                (float4*)out);
}

// round 9
// speedup vs baseline: 1.2357x; 1.2083x over previous
#include <cuda_runtime.h>
#include <math.h>

#define MM 256
#define DD 768
#define THRESH 0.3f
#define EPSF 1e-8f
#define KSPLIT 12
#define KPER (DD / KSPLIT)      // 64 k per gram block
#define NTILE 16                // 4x4 tiles of 64x64 over 256x256
#define NGRAM (KSPLIT * NTILE)  // 192 gram blocks

// ---------------- device scratch (no allocations allowed) ----------------
__device__ float g_nm2[MM];
__device__ float g_rnm[MM];
__device__ float g_Sm[MM];
__device__ float g_kx[MM];
__device__ float g_mask[MM];
__device__ float g_nx, g_Sx;
__device__ float g_kmp[KSPLIT][MM * MM];  // gram partials per K-split
__device__ float g_sT[MM * MM];           // s transposed: g_sT[i*MM + a]

// ---------------- K1: gram (64x64 tile, 4x4 micro, k-major smem) + stats ---
// grid = 449 blocks x 256 threads.
//   blocks [0,192):   gram partial. b = split*16 + tile. tile -> 64x64 output.
//   blocks [192,449): row stats (257 = MM rows + x).
__global__ void k_prep(const float* __restrict__ x, const float* __restrict__ mem) {
    int b = blockIdx.x, t = threadIdx.x;

    if (b < NGRAM) {
        // k-major shared: s[k][row], row dim padded 64->68 (16B-aligned rows,
        // conflict-free float4 reads at &s[k][4*tx]).
        __shared__ float sA[16][68];
        __shared__ float sB[16][68];
        int split = b >> 4;
        int tile = b & 15;
        int r0 = (tile >> 2) * 64, c0 = (tile & 3) * 64;
        int tx = t & 15, ty = t >> 4;          // 16x16 thread grid
        int lrow = t >> 2, lkq = t & 3;        // loader: row 0..63, k-quad 0..3
        const float4* mem4 = (const float4*)mem;   // row stride 192 float4
        int kqbase = split * (KPER / 4);       // float4 col base for this split

        float acc[4][4];
#pragma unroll
        for (int jy = 0; jy < 4; jy++)
#pragma unroll
            for (int jx = 0; jx < 4; jx++) acc[jy][jx] = 0.f;

        for (int kc = 0; kc < KPER; kc += 16) {
            // load+transpose: each thread one float4 of A and B
            float4 va = mem4[(r0 + lrow) * 192 + kqbase + (kc >> 2) + lkq];
            float4 vb = mem4[(c0 + lrow) * 192 + kqbase + (kc >> 2) + lkq];
            int kb = lkq * 4;
            sA[kb + 0][lrow] = va.x; sA[kb + 1][lrow] = va.y;
            sA[kb + 2][lrow] = va.z; sA[kb + 3][lrow] = va.w;
            sB[kb + 0][lrow] = vb.x; sB[kb + 1][lrow] = vb.y;
            sB[kb + 2][lrow] = vb.z; sB[kb + 3][lrow] = vb.w;
            __syncthreads();
#pragma unroll
            for (int k = 0; k < 16; k++) {
                float4 af = *(const float4*)&sA[k][ty << 2];
                float4 bf = *(const float4*)&sB[k][tx << 2];
                float a[4] = {af.x, af.y, af.z, af.w};
                float bb[4] = {bf.x, bf.y, bf.z, bf.w};
#pragma unroll
                for (int jy = 0; jy < 4; jy++)
#pragma unroll
                    for (int jx = 0; jx < 4; jx++)
                        acc[jy][jx] = fmaf(a[jy], bb[jx], acc[jy][jx]);
            }
            __syncthreads();
        }
        float* dst = g_kmp[split];
#pragma unroll
        for (int jy = 0; jy < 4; jy++) {
            float4 v = make_float4(acc[jy][0], acc[jy][1], acc[jy][2], acc[jy][3]);
            *(float4*)&dst[(r0 + (ty << 2) + jy) * MM + c0 + (tx << 2)] = v;
        }
    } else {
        int r = b - NGRAM;
        float s0 = 0.f, s1 = 0.f, s2 = 0.f;
        if (r < MM) {
            const float* row = mem + r * DD;
            for (int d = t; d < DD; d += 256) {
                float v = row[d], xv = x[d];
                s0 = fmaf(v, v, s0);
                s1 += v;
                s2 = fmaf(v, xv, s2);
            }
        } else {
            for (int d = t; d < DD; d += 256) {
                float xv = x[d];
                s0 = fmaf(xv, xv, s0);
                s1 += xv;
            }
        }
        __shared__ float sh[3][8];
#pragma unroll
        for (int o = 16; o; o >>= 1) {
            s0 += __shfl_down_sync(0xffffffffu, s0, o);
            s1 += __shfl_down_sync(0xffffffffu, s1, o);
            s2 += __shfl_down_sync(0xffffffffu, s2, o);
        }
        if ((t & 31) == 0) { int w = t >> 5; sh[0][w] = s0; sh[1][w] = s1; sh[2][w] = s2; }
        __syncthreads();
        if (t == 0) {
            float a = 0.f, c = 0.f, e = 0.f;
            for (int w = 0; w < 8; w++) { a += sh[0][w]; c += sh[1][w]; e += sh[2][w]; }
            if (r < MM) {
                g_nm2[r] = a;
                g_rnm[r] = 1.f / fmaxf(sqrtf(a), EPSF);
                g_Sm[r] = c;
                g_kx[r] = e;
            } else {
                g_nx = fmaxf(sqrtf(a), EPSF);
                g_Sx = c;
            }
        }
    }
}

// ---------------- K2: block i -> mask/cnt/A2 (local) + A1[i] + s[:, i] -----
__global__ void k_s(void) {
    __shared__ float red[3][8];
    __shared__ float sh_A1, sh_cnt, sh_A2;
    int i = blockIdx.x, t = threadIdx.x;

    float nx = g_nx;
    float rnmt = g_rnm[t];
    float mx_t = g_kx[t] * rnmt / nx;
    float mk = (mx_t > THRESH) ? 1.f : 0.f;
    float w = mk * rnmt;
    if (i == 0) g_mask[t] = mk;

    int off = i * MM + t;
    float kmv = 0.f;
#pragma unroll
    for (int s = 0; s < KSPLIT; s++) kmv += g_kmp[s][off];

    float r0 = mk;
    float r1 = mk * g_Sm[t] * rnmt;
    float r2 = kmv * w;
#pragma unroll
    for (int o = 16; o; o >>= 1) {
        r0 += __shfl_down_sync(0xffffffffu, r0, o);
        r1 += __shfl_down_sync(0xffffffffu, r1, o);
        r2 += __shfl_down_sync(0xffffffffu, r2, o);
    }
    if ((t & 31) == 0) { int wi = t >> 5; red[0][wi] = r0; red[1][wi] = r1; red[2][wi] = r2; }
    __syncthreads();
    if (t == 0) {
        float a = 0.f, bb = 0.f, c = 0.f;
        for (int wi = 0; wi < 8; wi++) { a += red[0][wi]; bb += red[1][wi]; c += red[2][wi]; }
        sh_cnt = a; sh_A2 = bb; sh_A1 = c;
    }
    __syncthreads();

    float rnmi = g_rnm[i];
    float kxi = g_kx[i];
    float c = kmv * rnmi * rnmt + kxi * rnmi / nx;
    float nkp = sqrtf(fmaxf(g_nm2[i] + 2.f * c * g_Sm[i] + (float)DD * c * c,
                            EPSF * EPSF));
    float ckx = (kxi + c * g_Sx) / (nkp * nx);
    float cnt = sh_cnt;
    float mean = (cnt > 0.f) ? (sh_A1 + c * sh_A2) / (nkp * fmaxf(cnt, 1.f)) : 0.f;
    g_sT[i * MM + t] = c + ckx + mean;
}

// ---------------- K3: streaming broadcast-add (HBM-bound) ------------------
__global__ void k_out(const float4* __restrict__ memv,
                      const float4* __restrict__ noise,
                      float4* __restrict__ out) {
    __shared__ float s_sh[32];
    __shared__ float m_sh[32];
    int i = blockIdx.x;
    int a0 = blockIdx.y << 5;
    int t = threadIdx.x;

    float4 mv = memv[i * 192 + t];

    if (t < 32) {
        m_sh[t] = g_mask[a0 + t];
        s_sh[t] = g_sT[i * MM + a0 + t];
    }
    __syncthreads();

#pragma unroll 8
    for (int q = 0; q < 32; q++) {
        int a = a0 + q;
        int base = (a * MM + i) * 192 + t;
        if (m_sh[q] != 0.f) {
            float s = s_sh[q];
            float4 nz = __ldcs(&noise[base]);
            float4 r;
            r.x = mv.x + s + nz.x;
            r.y = mv.y + s + nz.y;
            r.z = mv.z + s + nz.z;
            r.w = mv.w + s + nz.w;
            __stcs(&out[base], r);
        } else {
            __stcs(&out[base], make_float4(0.f, 0.f, 0.f, 0.f));
        }
    }
}

// ---------------- launch ----------------
extern "C" void kernel_launch(void* const* d_in, const int* in_sizes, int n_in,
                              void* d_out, int out_size) {
    const float* x     = (const float*)d_in[0];
    const float* mem   = (const float*)d_in[1];
    const float* noise = (const float*)d_in[2];
    float* out = (float*)d_out;

    k_prep<<<NGRAM + MM + 1, 256>>>(x, mem);
    k_s<<<MM, 256>>>();
    k_out<<<dim3(MM, 8), 192>>>((const float4*)mem, (const float4*)noise,
                                (float4*)out);
}

// round 11
// speedup vs baseline: 1.2447x; 1.0073x over previous
#include <cuda_runtime.h>
#include <math.h>

#define MM 256
#define DD 768
#define THRESH 0.3f
#define EPSF 1e-8f
#define KSPLIT 12
#define KPER (DD / KSPLIT)      // 64 k per gram block
#define NTILE 16                // 4x4 tiles of 64x64 over 256x256
#define NGRAM (KSPLIT * NTILE)  // 192 gram blocks

// ---------------- device scratch (no allocations allowed) ----------------
__device__ float g_nm2[MM];
__device__ float g_rnm[MM];
__device__ float g_Sm[MM];
__device__ float g_kx[MM];
__device__ float g_mask[MM];
__device__ float g_nx, g_Sx;
__device__ float g_kmp[KSPLIT][MM * MM];  // gram partials per K-split
__device__ float g_sT[MM * MM];           // s transposed: g_sT[i*MM + a]

// ---------------- K1: gram (64x64 tile, K=64 resident, 1 sync) + stats -----
// grid = 449 blocks x 256 threads.
//   blocks [0,192):   gram partial. b = split*16 + tile. tile -> 64x64 output.
//                     Whole K-slab staged in smem: load -> ONE sync -> 64-k FMA.
//   blocks [192,449): row stats (257 = MM rows + x).
__global__ void k_prep(const float* __restrict__ x, const float* __restrict__ mem) {
    int b = blockIdx.x, t = threadIdx.x;

    if (b < NGRAM) {
        // k-major shared: s[k][row], 64 k-rows, row dim padded 64->68.
        __shared__ float sA[64][68];
        __shared__ float sB[64][68];
        int split = b >> 4;
        int tile = b & 15;
        int r0 = (tile >> 2) * 64, c0 = (tile & 3) * 64;
        int tx = t & 15, ty = t >> 4;          // 16x16 thread grid
        int lrow = t >> 2, lkq = t & 3;        // loader: row 0..63, k-quad 0..3
        const float4* mem4 = (const float4*)mem;   // row stride 192 float4
        int kqbase = split * (KPER / 4);       // float4 col base for this split

        // front-batched loads: 4 float4 of A + 4 of B per thread (MLP=8)
        float4 va[4], vb[4];
#pragma unroll
        for (int j = 0; j < 4; j++) {
            int kq = lkq + 4 * j;              // 0..15 float4 within K-slab
            va[j] = mem4[(r0 + lrow) * 192 + kqbase + kq];
            vb[j] = mem4[(c0 + lrow) * 192 + kqbase + kq];
        }
#pragma unroll
        for (int j = 0; j < 4; j++) {
            int kb = (lkq + 4 * j) * 4;        // k index of this float4
            sA[kb + 0][lrow] = va[j].x; sA[kb + 1][lrow] = va[j].y;
            sA[kb + 2][lrow] = va[j].z; sA[kb + 3][lrow] = va[j].w;
            sB[kb + 0][lrow] = vb[j].x; sB[kb + 1][lrow] = vb[j].y;
            sB[kb + 2][lrow] = vb[j].z; sB[kb + 3][lrow] = vb[j].w;
        }
        __syncthreads();                       // the ONLY barrier

        float acc[4][4];
#pragma unroll
        for (int jy = 0; jy < 4; jy++)
#pragma unroll
            for (int jx = 0; jx < 4; jx++) acc[jy][jx] = 0.f;

#pragma unroll 8
        for (int k = 0; k < 64; k++) {
            float4 af = *(const float4*)&sA[k][ty << 2];
            float4 bf = *(const float4*)&sB[k][tx << 2];
            float a[4] = {af.x, af.y, af.z, af.w};
            float bb[4] = {bf.x, bf.y, bf.z, bf.w};
#pragma unroll
            for (int jy = 0; jy < 4; jy++)
#pragma unroll
                for (int jx = 0; jx < 4; jx++)
                    acc[jy][jx] = fmaf(a[jy], bb[jx], acc[jy][jx]);
        }

        float* dst = g_kmp[split];
#pragma unroll
        for (int jy = 0; jy < 4; jy++) {
            float4 v = make_float4(acc[jy][0], acc[jy][1], acc[jy][2], acc[jy][3]);
            *(float4*)&dst[(r0 + (ty << 2) + jy) * MM + c0 + (tx << 2)] = v;
        }
    } else {
        int r = b - NGRAM;
        float s0 = 0.f, s1 = 0.f, s2 = 0.f;
        if (r < MM) {
            const float* row = mem + r * DD;
            for (int d = t; d < DD; d += 256) {
                float v = row[d], xv = x[d];
                s0 = fmaf(v, v, s0);
                s1 += v;
                s2 = fmaf(v, xv, s2);
            }
        } else {
            for (int d = t; d < DD; d += 256) {
                float xv = x[d];
                s0 = fmaf(xv, xv, s0);
                s1 += xv;
            }
        }
        __shared__ float sh[3][8];
#pragma unroll
        for (int o = 16; o; o >>= 1) {
            s0 += __shfl_down_sync(0xffffffffu, s0, o);
            s1 += __shfl_down_sync(0xffffffffu, s1, o);
            s2 += __shfl_down_sync(0xffffffffu, s2, o);
        }
        if ((t & 31) == 0) { int w = t >> 5; sh[0][w] = s0; sh[1][w] = s1; sh[2][w] = s2; }
        __syncthreads();
        if (t == 0) {
            float a = 0.f, c = 0.f, e = 0.f;
            for (int w = 0; w < 8; w++) { a += sh[0][w]; c += sh[1][w]; e += sh[2][w]; }
            if (r < MM) {
                g_nm2[r] = a;
                g_rnm[r] = 1.f / fmaxf(sqrtf(a), EPSF);
                g_Sm[r] = c;
                g_kx[r] = e;
            } else {
                g_nx = fmaxf(sqrtf(a), EPSF);
                g_Sx = c;
            }
        }
    }
}

// ---------------- K2: block i -> mask/cnt/A2 (local) + A1[i] + s[:, i] -----
__global__ void k_s(void) {
    __shared__ float red[3][8];
    __shared__ float sh_A1, sh_cnt, sh_A2;
    int i = blockIdx.x, t = threadIdx.x;

    float nx = g_nx;
    float rnmt = g_rnm[t];
    float mx_t = g_kx[t] * rnmt / nx;
    float mk = (mx_t > THRESH) ? 1.f : 0.f;
    float w = mk * rnmt;
    if (i == 0) g_mask[t] = mk;

    int off = i * MM + t;
    float kmv = 0.f;
#pragma unroll
    for (int s = 0; s < KSPLIT; s++) kmv += g_kmp[s][off];

    float r0 = mk;
    float r1 = mk * g_Sm[t] * rnmt;
    float r2 = kmv * w;
#pragma unroll
    for (int o = 16; o; o >>= 1) {
        r0 += __shfl_down_sync(0xffffffffu, r0, o);
        r1 += __shfl_down_sync(0xffffffffu, r1, o);
        r2 += __shfl_down_sync(0xffffffffu, r2, o);
    }
    if ((t & 31) == 0) { int wi = t >> 5; red[0][wi] = r0; red[1][wi] = r1; red[2][wi] = r2; }
    __syncthreads();
    if (t == 0) {
        float a = 0.f, bb = 0.f, c = 0.f;
        for (int wi = 0; wi < 8; wi++) { a += red[0][wi]; bb += red[1][wi]; c += red[2][wi]; }
        sh_cnt = a; sh_A2 = bb; sh_A1 = c;
    }
    __syncthreads();

    float rnmi = g_rnm[i];
    float kxi = g_kx[i];
    float c = kmv * rnmi * rnmt + kxi * rnmi / nx;
    float nkp = sqrtf(fmaxf(g_nm2[i] + 2.f * c * g_Sm[i] + (float)DD * c * c,
                            EPSF * EPSF));
    float ckx = (kxi + c * g_Sx) / (nkp * nx);
    float cnt = sh_cnt;
    float mean = (cnt > 0.f) ? (sh_A1 + c * sh_A2) / (nkp * fmaxf(cnt, 1.f)) : 0.f;
    g_sT[i * MM + t] = c + ckx + mean;
}

// ---------------- K3: streaming broadcast-add (HBM-bound) ------------------
__global__ void k_out(const float4* __restrict__ memv,
                      const float4* __restrict__ noise,
                      float4* __restrict__ out) {
    __shared__ float s_sh[32];
    __shared__ float m_sh[32];
    int i = blockIdx.x;
    int a0 = blockIdx.y << 5;
    int t = threadIdx.x;

    float4 mv = memv[i * 192 + t];

    if (t < 32) {
        m_sh[t] = g_mask[a0 + t];
        s_sh[t] = g_sT[i * MM + a0 + t];
    }
    __syncthreads();

#pragma unroll 8
    for (int q = 0; q < 32; q++) {
        int a = a0 + q;
        int base = (a * MM + i) * 192 + t;
        if (m_sh[q] != 0.f) {
            float s = s_sh[q];
            float4 nz = __ldcs(&noise[base]);
            float4 r;
            r.x = mv.x + s + nz.x;
            r.y = mv.y + s + nz.y;
            r.z = mv.z + s + nz.z;
            r.w = mv.w + s + nz.w;
            __stcs(&out[base], r);
        } else {
            __stcs(&out[base], make_float4(0.f, 0.f, 0.f, 0.f));
        }
    }
}

// ---------------- launch ----------------
extern "C" void kernel_launch(void* const* d_in, const int* in_sizes, int n_in,
                              void* d_out, int out_size) {
    const float* x     = (const float*)d_in[0];
    const float* mem   = (const float*)d_in[1];
    const float* noise = (const float*)d_in[2];
    float* out = (float*)d_out;

    k_prep<<<NGRAM + MM + 1, 256>>>(x, mem);
    k_s<<<MM, 256>>>();
    k_out<<<dim3(MM, 8), 192>>>((const float4*)mem, (const float4*)noise,
                                (float4*)out);
}